// round 1
// baseline (speedup 1.0000x reference)
#include <cuda_runtime.h>
#include <cuda_bf16.h>

// One 256-thread block per 1024-element row. float4 I/O, register-resident row
// slice (4 elems/thread), exact integer row-sum, reciprocal-mul fast paths.

__global__ __launch_bounds__(256, 8) void qsoftmax_kernel(
    const float* __restrict__ x,
    const float* __restrict__ scale_p,
    const float* __restrict__ thr_p,
    float* __restrict__ out)
{
    const size_t row = blockIdx.x;
    const float4* __restrict__ xin = reinterpret_cast<const float4*>(x + row * 1024);
    float4* __restrict__ ov       = reinterpret_cast<float4*>(out + row * 1024);
    const int t    = threadIdx.x;
    const int lane = t & 31;
    const int wid  = t >> 5;

    const float sf     = *scale_p;       // uniform, L2/constant-cached
    const float inv_sf = 1.0f / sf;

    float4 v = xin[t];
    float aa[4];
    aa[0] = v.x * inv_sf;
    aa[1] = v.y * inv_sf;
    aa[2] = v.z * inv_sf;
    aa[3] = v.w * inv_sf;

    // ---- row max ----
    float m = fmaxf(fmaxf(aa[0], aa[1]), fmaxf(aa[2], aa[3]));
    #pragma unroll
    for (int o = 16; o > 0; o >>= 1)
        m = fmaxf(m, __shfl_xor_sync(0xffffffffu, m, o));

    __shared__ float smax[8];
    __shared__ unsigned long long ssum[8];
    if (lane == 0) smax[wid] = m;
    __syncthreads();
    float rmax = smax[0];
    #pragma unroll
    for (int i = 1; i < 8; i++) rmax = fmaxf(rmax, smax[i]);

    // ---- integer-exp constants (uniform; true f32 divs in reference order) ----
    const float x0_int = floorf(-0.69314718f / sf);                       // -14 @ sf=0.05
    const float b_int  = floorf((float)(0.96963238 / 0.35815147) / sf);   // 54
    const float c_int  = floorf((float)(1.0 / 0.35815147) / (sf * sf));   // 1116
    const float lo     = 15.0f * x0_int;                                  // -210
    const float inv_x0 = 1.0f / x0_int;

    // ---- per-element integer exp; exact integer partial sum ----
    float e[4];
    unsigned int psum = 0;
    #pragma unroll
    for (int i = 0; i < 4; i++) {
        float xi = fmaxf(aa[i] - rmax, lo);          // <= 0, >= 15*x0_int
        float qf = floorf(xi * inv_x0);              // q in [0,15]
        int   qi = (int)qf;
        float r  = xi - x0_int * qf;
        float z  = r * (r + b_int) + c_int;          // in [~388, ~2000], > 0
        float p2 = __int_as_float((142 - qi) << 23); // exact 2^(15-q)
        float ei = fmaxf(floorf(z * p2), 0.0f);      // exact int <= 2^26
        e[i] = ei;
        psum += (unsigned int)ei;                    // 4 * 2^26 < 2^31: no overflow
    }

    // ---- exact row sum (u64) ----
    unsigned long long s = psum;
    #pragma unroll
    for (int o = 16; o > 0; o >>= 1)
        s += __shfl_xor_sync(0xffffffffu, s, o);
    if (lane == 0) ssum[wid] = s;
    __syncthreads();
    unsigned long long tot = 0;
    #pragma unroll
    for (int i = 0; i < 8; i++) tot += ssum[i];

    // ---- per-row epilogue scalars (uniform) ----
    const float sum_f  = (float)tot;                        // RN u64->f32
    const float factor = floorf(4294967296.0f / sum_f);
    const float thr    = *thr_p;
    const float t8     = floorf(thr * 256.0f);
    const float approx = (t8 * sum_f) / 256.0f;             // ref op order: (t8*sum)/256
    const float osA    = thr / 255.0f;
    const float osB    = (float)(1.0 / 255.0);              // weak-promoted double->f32
    const float denA   = 4294967296.0f * osA;
    const float denB   = (float)(4294967296.0 / 255.0);     // weak-promoted double->f32
    const float invA   = 1.0f / denA;
    const float invB   = 1.0f / denB;

    // ---- per-element quantized output ----
    float o4[4];
    #pragma unroll
    for (int i = 0; i < 4; i++) {
        float ei = e[i];
        float sc = ei * factor;                              // <= 2^32, fine in f32
        float r;
        if (ei <= approx) {
            r = floorf(sc * invA) * osA;                     // A branch (B term is 0)
        } else {
            r = fminf(floorf(sc * invB), 255.0f) * osB;      // B branch (A term is 0)
        }
        o4[i] = r;
    }
    float4 w;
    w.x = o4[0]; w.y = o4[1]; w.z = o4[2]; w.w = o4[3];
    ov[t] = w;
}

extern "C" void kernel_launch(void* const* d_in, const int* in_sizes, int n_in,
                              void* d_out, int out_size) {
    const float* x     = (const float*)d_in[0];
    const float* scale = (const float*)d_in[1];
    const float* thr   = (const float*)d_in[2];
    float* out = (float*)d_out;
    const int rows = out_size / 1024;   // 32768
    qsoftmax_kernel<<<rows, 256>>>(x, scale, thr, out);
}

// round 2
// speedup vs baseline: 1.3319x; 1.3319x over previous
#include <cuda_runtime.h>
#include <cuda_bf16.h>

// Uniform scalars derived from (scale, threshold), computed once by a 1-thread
// setup kernel so the 8.4M-thread main kernel never executes f32 divisions for
// them. 12 floats, loaded as 3x LDG.128.
struct __align__(16) QConsts {
    float inv_sf, x0_int, b_int, c_int;   // c0
    float inv_x0, lo,     thr,   t8;      // c1
    float osA,    osB,    invA,  invB;    // c2
};
__device__ QConsts g_c;

__global__ void qsoftmax_setup(const float* __restrict__ scale_p,
                               const float* __restrict__ thr_p)
{
    const float sf  = *scale_p;
    const float thr = *thr_p;
    const float x0  = floorf(-0.69314718f / sf);
    QConsts c;
    c.inv_sf = 1.0f / sf;
    c.x0_int = x0;
    c.b_int  = floorf((float)(0.96963238 / 0.35815147) / sf);
    c.c_int  = floorf((float)(1.0 / 0.35815147) / (sf * sf));
    c.inv_x0 = 1.0f / x0;
    c.lo     = 15.0f * x0;
    c.thr    = thr;
    c.t8     = floorf(thr * 256.0f);
    const float osA = thr / 255.0f;
    c.osA  = osA;
    c.osB  = (float)(1.0 / 255.0);                 // weak-promoted double->f32
    c.invA = 1.0f / (4294967296.0f * osA);
    c.invB = 1.0f / (float)(4294967296.0 / 255.0); // weak-promoted double->f32
    g_c = c;
}

// One 256-thread block per 1024-element row; 4 elems/thread, float4 I/O.
__global__ __launch_bounds__(256, 8) void qsoftmax_kernel(
    const float* __restrict__ x,
    float* __restrict__ out)
{
    const size_t row = blockIdx.x;
    const float4* __restrict__ xin = reinterpret_cast<const float4*>(x + row * 1024);
    float4* __restrict__ ov        = reinterpret_cast<float4*>(out + row * 1024);
    const int t    = threadIdx.x;
    const int lane = t & 31;
    const int wid  = t >> 5;

    // Uniform constants: 3 vector loads, L2-resident.
    const float4* cp = reinterpret_cast<const float4*>(&g_c);
    const float4 c0 = cp[0];   // inv_sf, x0_int, b_int, c_int
    const float4 c1 = cp[1];   // inv_x0, lo, thr, t8
    const float4 c2 = cp[2];   // osA, osB, invA, invB

    float4 v = xin[t];
    float aa[4];
    aa[0] = v.x * c0.x;
    aa[1] = v.y * c0.x;
    aa[2] = v.z * c0.x;
    aa[3] = v.w * c0.x;

    // ---- row max: warp shfl tree + one shared round ----
    float m = fmaxf(fmaxf(aa[0], aa[1]), fmaxf(aa[2], aa[3]));
    #pragma unroll
    for (int o = 16; o > 0; o >>= 1)
        m = fmaxf(m, __shfl_xor_sync(0xffffffffu, m, o));

    __shared__ float smax[8];
    __shared__ float ssum[8];
    if (lane == 0) smax[wid] = m;
    __syncthreads();
    float rmax = smax[0];
    #pragma unroll
    for (int i = 1; i < 8; i++) rmax = fmaxf(rmax, smax[i]);

    // ---- per-element integer exp ----
    float e[4];
    #pragma unroll
    for (int i = 0; i < 4; i++) {
        float xi = fmaxf(aa[i] - rmax, c1.y);        // clamp at 15*x0_int
        float qf = floorf(xi * c1.x);                // q in [0,15]
        int   qi = (int)qf;
        float r  = xi - c0.y * qf;                   // remainder, in (x0,0]
        float z  = r * (r + c0.z) + c0.w;            // int polynomial, > 0
        float p2 = __int_as_float((142 - qi) << 23); // exact 2^(15-q)
        e[i] = fmaxf(floorf(z * p2), 0.0f);          // exact integer <= ~2^25.2
    }

    // ---- f32 row sum (exp values are exact ints; f32 rounding ~1e-7 rel) ----
    float s = (e[0] + e[1]) + (e[2] + e[3]);
    #pragma unroll
    for (int o = 16; o > 0; o >>= 1)
        s += __shfl_xor_sync(0xffffffffu, s, o);
    if (lane == 0) ssum[wid] = s;
    __syncthreads();
    float sum_f = ssum[0];
    #pragma unroll
    for (int i = 1; i < 8; i++) sum_f += ssum[i];

    // ---- per-row scalars (one true division: factor) ----
    const float factor = floorf(4294967296.0f / sum_f);
    const float approx = (c1.w * sum_f) * 0.00390625f;   // floor(thr*256)*sum/256

    // ---- per-element quantized output (branchless select) ----
    float o4[4];
    #pragma unroll
    for (int i = 0; i < 4; i++) {
        float ei = e[i];
        float sc = ei * factor;
        float ra = floorf(sc * c2.z) * c2.x;                  // A path
        float rb = fminf(floorf(sc * c2.w), 255.0f) * c2.y;   // B path
        o4[i] = (ei <= approx) ? ra : rb;
    }
    float4 w;
    w.x = o4[0]; w.y = o4[1]; w.z = o4[2]; w.w = o4[3];
    ov[t] = w;
}

extern "C" void kernel_launch(void* const* d_in, const int* in_sizes, int n_in,
                              void* d_out, int out_size) {
    const float* x     = (const float*)d_in[0];
    const float* scale = (const float*)d_in[1];
    const float* thr   = (const float*)d_in[2];
    float* out = (float*)d_out;
    const int rows = out_size / 1024;   // 32768
    qsoftmax_setup<<<1, 1>>>(scale, thr);
    qsoftmax_kernel<<<rows, 256>>>(x, out);
}

// round 5
// speedup vs baseline: 1.7108x; 1.2845x over previous
#include <cuda_runtime.h>
#include <cuda_bf16.h>

// Uniform scalars derived from (scale, threshold), computed once by a 1-thread
// setup kernel. 12 floats, loaded by the main kernel as 3x LDG.128.
struct __align__(16) QConsts {
    float inv_sf, x0_int, b_int, c_int;   // c0
    float inv_x0, lo,     thr,   t8;      // c1
    float osA,    osB,    invA,  invB;    // c2
};
__device__ QConsts g_c;

__global__ void qsoftmax_setup(const float* __restrict__ scale_p,
                               const float* __restrict__ thr_p)
{
    const float sf  = *scale_p;
    const float thr = *thr_p;
    const float x0  = floorf(-0.69314718f / sf);
    QConsts c;
    c.inv_sf = 1.0f / sf;
    c.x0_int = x0;
    c.b_int  = floorf((float)(0.96963238 / 0.35815147) / sf);
    c.c_int  = floorf((float)(1.0 / 0.35815147) / (sf * sf));
    c.inv_x0 = 1.0f / x0;
    c.lo     = 15.0f * x0;
    c.thr    = thr;
    c.t8     = floorf(thr * 256.0f);
    const float osA = thr / 255.0f;
    c.osA  = osA;
    c.osB  = (float)(1.0 / 255.0);                 // weak-promoted double->f32
    c.invA = 1.0f / (4294967296.0f * osA);
    c.invB = 1.0f / (float)(4294967296.0 / 255.0); // weak-promoted double->f32
    g_c = c;
}

// One warp per 1024-element row: 32 elems/thread, 8x float4 I/O, shuffle-only
// reductions (no shared memory, no __syncthreads).
__global__ __launch_bounds__(256, 4) void qsoftmax_kernel(
    const float* __restrict__ x,
    float* __restrict__ out,
    int rows)
{
    const int lane = threadIdx.x & 31;
    const int wid  = threadIdx.x >> 5;
    const int row  = blockIdx.x * 8 + wid;
    if (row >= rows) return;

    const float4* __restrict__ xin = reinterpret_cast<const float4*>(x)   + (size_t)row * 256;
    float4* __restrict__ ov        = reinterpret_cast<float4*>(out)       + (size_t)row * 256;

    const float4* cp = reinterpret_cast<const float4*>(&g_c);
    const float4 c0 = cp[0];   // inv_sf, x0_int, b_int, c_int
    const float4 c1 = cp[1];   // inv_x0, lo, thr, t8
    const float4 c2 = cp[2];   // osA, osB, invA, invB
    const float inv_sf = c0.x, x0i = c0.y, b_int = c0.z, c_int = c0.w;
    const float inv_x0 = c1.x, lo = c1.y, t8 = c1.w;
    const float osA = c2.x, osB = c2.y, invA = c2.z, invB = c2.w;

    // ---- load full row slice (MLP=8) ----
    float4 v[8];
    #pragma unroll
    for (int i = 0; i < 8; i++) v[i] = xin[lane + 32 * i];

    // ---- row max over raw x (RN mul by inv_sf>0 is monotonic) ----
    float m = fmaxf(fmaxf(v[0].x, v[0].y), fmaxf(v[0].z, v[0].w));
    #pragma unroll
    for (int i = 1; i < 8; i++)
        m = fmaxf(m, fmaxf(fmaxf(v[i].x, v[i].y), fmaxf(v[i].z, v[i].w)));
    #pragma unroll
    for (int o = 16; o > 0; o >>= 1)
        m = fmaxf(m, __shfl_xor_sync(0xffffffffu, m, o));
    const float rmaxs = m * inv_sf;    // = max over (x*inv_sf)

    // ---- integer exp, in place; f32 running sum ----
    float s0 = 0.0f, s1 = 0.0f;
    #pragma unroll
    for (int i = 0; i < 8; i++) {
        float* e = reinterpret_cast<float*>(&v[i]);
        #pragma unroll
        for (int cidx = 0; cidx < 4; cidx++) {
            float xi = fmaxf(fmaf(e[cidx], inv_sf, -rmaxs), lo);  // <= 0
            float y  = xi * inv_x0;                                // >= 0
            int   qi = (int)y;                                     // trunc == floor
            float qf = (float)qi;
            float r  = fmaf(-x0i, qf, xi);
            float z  = fmaf(r, r + b_int, c_int);                  // > 0
            float p2 = __int_as_float(0x47000000 - (qi << 23));    // exact 2^(15-q)
            float ei = fmaxf(floorf(z * p2), 0.0f);                // exact int <= ~2^25.2
            e[cidx] = ei;
            if (cidx & 1) s1 += ei; else s0 += ei;
        }
    }
    float s = s0 + s1;
    #pragma unroll
    for (int o = 16; o > 0; o >>= 1)
        s += __shfl_xor_sync(0xffffffffu, s, o);

    // ---- per-row scalars (one true division) ----
    const float factor = floorf(4294967296.0f / s);
    const float approx = (t8 * s) * 0.00390625f;     // floor(thr*256)*sum/256

    // ---- quantized output: predicated constant select, single floor path ----
    #pragma unroll
    for (int i = 0; i < 8; i++) {
        float* e = reinterpret_cast<float*>(&v[i]);
        #pragma unroll
        for (int cidx = 0; cidx < 4; cidx++) {
            float ei   = e[cidx];
            bool  isA  = (ei <= approx);
            float inv  = isA ? invA : invB;
            float os   = isA ? osA  : osB;
            float cap  = isA ? 3.0e38f : 255.0f;
            float q    = fminf(floorf((ei * factor) * inv), cap);
            e[cidx] = q * os;
        }
        ov[lane + 32 * i] = v[i];
    }
}

extern "C" void kernel_launch(void* const* d_in, const int* in_sizes, int n_in,
                              void* d_out, int out_size) {
    const float* x     = (const float*)d_in[0];
    const float* scale = (const float*)d_in[1];
    const float* thr   = (const float*)d_in[2];
    float* out = (float*)d_out;
    const int rows = out_size / 1024;   // 32768
    qsoftmax_setup<<<1, 1>>>(scale, thr);
    qsoftmax_kernel<<<(rows + 7) / 8, 256>>>(x, out, rows);
}

// round 7
// speedup vs baseline: 1.7585x; 1.0279x over previous
#include <cuda_runtime.h>
#include <cuda_bf16.h>

// One warp per 1024-element row: 32 elems/thread, 8x float4 I/O, shuffle-only
// reductions. All scale/threshold-derived scalars computed inline (uniform
// datapath); zero conversion-pipe instructions in the per-element path.

__device__ __forceinline__ float floor_small(float w) {
    // floor for 0 <= w < 2^23 - 1, no conversion instructions
    float t = w + 8388608.0f;       // round-to-nearest integer
    float u = t - 8388608.0f;
    return (u > w) ? u - 1.0f : u;
}

__global__ __launch_bounds__(256, 4) void qsoftmax_kernel(
    const float* __restrict__ x,
    const float* __restrict__ scale_p,
    const float* __restrict__ thr_p,
    float* __restrict__ out,
    int rows)
{
    const int lane = threadIdx.x & 31;
    const int wid  = threadIdx.x >> 5;
    const int row  = blockIdx.x * 8 + wid;
    if (row >= rows) return;

    const float4* __restrict__ xin = reinterpret_cast<const float4*>(x)  + (size_t)row * 256;
    float4* __restrict__ ov        = reinterpret_cast<float4*>(out)      + (size_t)row * 256;

    // ---- load full row slice first (MLP=8) ----
    float4 v[8];
    #pragma unroll
    for (int i = 0; i < 8; i++) v[i] = xin[lane + 32 * i];

    // ---- uniform constants (thread-invariant; uniform-datapath friendly) ----
    const float sf     = *scale_p;
    const float thr    = *thr_p;
    const float inv_sf = 1.0f / sf;
    const float x0i    = floor_small(-0.69314718f / sf + 16384.0f) - 16384.0f;
    const float b_int  = floor_small((float)(0.96963238 / 0.35815147) / sf);
    const float c_int  = floor_small((float)(1.0 / 0.35815147) / (sf * sf));
    const float inv_x0 = 1.0f / x0i;
    const float lo     = 15.0f * x0i;
    const float t8     = floor_small(thr * 256.0f);
    const float osA    = thr / 255.0f;
    const float osB    = (float)(1.0 / 255.0);                  // weak-promoted
    const float invA   = 1.0f / (4294967296.0f * osA);
    const float invB   = 1.0f / (float)(4294967296.0 / 255.0);  // weak-promoted

    // ---- row max over raw x (RN mul by inv_sf>0 is monotonic) ----
    float m = fmaxf(fmaxf(v[0].x, v[0].y), fmaxf(v[0].z, v[0].w));
    #pragma unroll
    for (int i = 1; i < 8; i++)
        m = fmaxf(m, fmaxf(fmaxf(v[i].x, v[i].y), fmaxf(v[i].z, v[i].w)));
    #pragma unroll
    for (int o = 16; o > 0; o >>= 1)
        m = fmaxf(m, __shfl_xor_sync(0xffffffffu, m, o));
    const float rmaxs = m * inv_sf;

    // ---- integer exp, in place; f32 running sum; zero conversion ops ----
    float s0 = 0.0f, s1 = 0.0f;
    #pragma unroll
    for (int i = 0; i < 8; i++) {
        float* e = reinterpret_cast<float*>(&v[i]);
        #pragma unroll
        for (int cidx = 0; cidx < 4; cidx++) {
            float xi = fmaxf(fmaf(e[cidx], inv_sf, -rmaxs), lo);   // ~[15*x0, +eps]
            // y clamped at 0: the row-max element's fma residual can be +eps,
            // which makes y slightly NEGATIVE (inv_x0 < 0); floor(-eps) = -1
            // would corrupt q for the dominant element (round-6 bug).
            float y  = fmaxf(xi * inv_x0, 0.0f);                    // in [0, 15]
            // floor(y) via magic: integer in mantissa bits, float via subtract
            float ty = y + 8388608.0f;
            int   qr = __float_as_int(ty) - 0x4B000000;             // round(y)
            float qf = ty - 8388608.0f;
            bool  adj = (qf > y);
            qf = adj ? qf - 1.0f : qf;
            int  qi = adj ? qr - 1 : qr;                            // q in [0,15]
            float r  = fmaf(-x0i, qf, xi);
            float z  = fmaf(r, r + b_int, c_int);                   // in [~556, 1116]
            float p2 = __int_as_float(0x47000000 - (qi << 23));     // exact 2^(15-q)
            float ei = z * p2;            // unfloored: frac < 1 << quant step
            e[cidx] = ei;
            if (cidx & 1) s1 += ei; else s0 += ei;
        }
    }
    float s = s0 + s1;
    #pragma unroll
    for (int o = 16; o > 0; o >>= 1)
        s += __shfl_xor_sync(0xffffffffu, s, o);

    // ---- per-row scalars (one true division) ----
    const float factor = floor_small(4294967296.0f / s);
    const float approx = (t8 * s) * 0.00390625f;    // floor(thr*256)*sum/256

    // ---- quantized output: predicated selects, magic floor (w < ~520) ----
    #pragma unroll
    for (int i = 0; i < 8; i++) {
        float* e = reinterpret_cast<float*>(&v[i]);
        #pragma unroll
        for (int cidx = 0; cidx < 4; cidx++) {
            float ei  = e[cidx];
            bool  isA = (ei <= approx);
            float inv = isA ? invA : invB;
            float os  = isA ? osA  : osB;
            float cap = isA ? 3.0e38f : 255.0f;
            float w   = (ei * factor) * inv;
            float t   = w + 8388608.0f;
            float u   = t - 8388608.0f;
            u = (u > w) ? u - 1.0f : u;        // floor(w)
            e[cidx] = fminf(u, cap) * os;
        }
        ov[lane + 32 * i] = v[i];
    }
}

extern "C" void kernel_launch(void* const* d_in, const int* in_sizes, int n_in,
                              void* d_out, int out_size) {
    const float* x     = (const float*)d_in[0];
    const float* scale = (const float*)d_in[1];
    const float* thr   = (const float*)d_in[2];
    float* out = (float*)d_out;
    const int rows = out_size / 1024;   // 32768
    qsoftmax_kernel<<<(rows + 7) / 8, 256>>>(x, scale, thr, out, rows);
}

// round 8
// speedup vs baseline: 1.7872x; 1.0163x over previous
#include <cuda_runtime.h>
#include <cuda_bf16.h>

// One warp per 1024-element row: 32 elems/thread, 8x float4 I/O, shuffle-only
// reductions, single launch. Per-element path uses native conversion-pipe ops
// (F2I/I2F/FRND, 1 instr each) instead of ALU magic-floor sequences (round-7
// regression: alu pipe hit 58%), and drops the exp-floor + max(,0) (boundary-
// only effect, validated in round 7).

__global__ __launch_bounds__(256, 4) void qsoftmax_kernel(
    const float* __restrict__ x,
    const float* __restrict__ scale_p,
    const float* __restrict__ thr_p,
    float* __restrict__ out,
    int rows)
{
    const int lane = threadIdx.x & 31;
    const int wid  = threadIdx.x >> 5;
    const int row  = blockIdx.x * 8 + wid;
    if (row >= rows) return;

    const float4* __restrict__ xin = reinterpret_cast<const float4*>(x)  + (size_t)row * 256;
    float4* __restrict__ ov        = reinterpret_cast<float4*>(out)      + (size_t)row * 256;

    // ---- load full row slice first (MLP=8) ----
    float4 v[8];
    #pragma unroll
    for (int i = 0; i < 8; i++) v[i] = xin[lane + 32 * i];

    // ---- uniform constants (thread-invariant; ~40 instrs, amortized 1/elem) ----
    const float sf     = *scale_p;
    const float thr    = *thr_p;
    const float inv_sf = 1.0f / sf;
    const float x0i    = floorf(-0.69314718f / sf);
    const float b_int  = floorf((float)(0.96963238 / 0.35815147) / sf);
    const float c_int  = floorf((float)(1.0 / 0.35815147) / (sf * sf));
    const float inv_x0 = 1.0f / x0i;
    const float lo     = 15.0f * x0i;
    const float t8     = floorf(thr * 256.0f);
    const float osA    = thr / 255.0f;
    const float osB    = (float)(1.0 / 255.0);                  // weak-promoted
    const float invA   = 1.0f / (4294967296.0f * osA);
    const float invB   = 1.0f / (float)(4294967296.0 / 255.0);  // weak-promoted

    // ---- row max over raw x (RN mul by inv_sf>0 is monotonic) ----
    float m = fmaxf(fmaxf(v[0].x, v[0].y), fmaxf(v[0].z, v[0].w));
    #pragma unroll
    for (int i = 1; i < 8; i++)
        m = fmaxf(m, fmaxf(fmaxf(v[i].x, v[i].y), fmaxf(v[i].z, v[i].w)));
    #pragma unroll
    for (int o = 16; o > 0; o >>= 1)
        m = fmaxf(m, __shfl_xor_sync(0xffffffffu, m, o));
    const float rmaxs = m * inv_sf;

    // ---- integer exp, in place; f32 running sums ----
    float s0 = 0.0f, s1 = 0.0f;
    #pragma unroll
    for (int i = 0; i < 8; i++) {
        float* e = reinterpret_cast<float*>(&v[i]);
        #pragma unroll
        for (int cidx = 0; cidx < 4; cidx++) {
            float xi = fmaxf(fmaf(e[cidx], inv_sf, -rmaxs), lo);  // ~[15*x0, +eps]
            float y  = xi * inv_x0;                    // [-eps, 15]; trunc(-eps)=0 safe
            int   qi = (int)y;                         // F2I (trunc == floor on [0,15])
            float qf = (float)qi;                      // I2F
            float r  = fmaf(-x0i, qf, xi);
            float z  = fmaf(r, r + b_int, c_int);      // in [~556, 1116] > 0
            float p2 = __int_as_float(0x47000000 - (qi << 23));   // exact 2^(15-q)
            float ei = z * p2;                         // unfloored: frac<1 << quant step
            e[cidx] = ei;
            if (cidx & 1) s1 += ei; else s0 += ei;
        }
    }
    float s = s0 + s1;
    #pragma unroll
    for (int o = 16; o > 0; o >>= 1)
        s += __shfl_xor_sync(0xffffffffu, s, o);

    // ---- per-row scalars (one true division) ----
    const float factor = floorf(4294967296.0f / s);
    const float approx = (t8 * s) * 0.00390625f;       // floor(thr*256)*sum/256

    // ---- quantized output: predicated selects, native FRND floor ----
    #pragma unroll
    for (int i = 0; i < 8; i++) {
        float* e = reinterpret_cast<float*>(&v[i]);
        #pragma unroll
        for (int cidx = 0; cidx < 4; cidx++) {
            float ei  = e[cidx];
            bool  isA = (ei <= approx);
            float inv = isA ? invA : invB;
            float os  = isA ? osA  : osB;
            float cap = isA ? 3.0e38f : 255.0f;
            float q   = fminf(floorf((ei * factor) * inv), cap);
            e[cidx] = q * os;
        }
        ov[lane + 32 * i] = v[i];
    }
}

extern "C" void kernel_launch(void* const* d_in, const int* in_sizes, int n_in,
                              void* d_out, int out_size) {
    const float* x     = (const float*)d_in[0];
    const float* scale = (const float*)d_in[1];
    const float* thr   = (const float*)d_in[2];
    float* out = (float*)d_out;
    const int rows = out_size / 1024;   // 32768
    qsoftmax_kernel<<<(rows + 7) / 8, 256>>>(x, scale, thr, out, rows);
}